// round 1
// baseline (speedup 1.0000x reference)
#include <cuda_runtime.h>
#include <math.h>

// Problem dims (fixed by the reference setup)
#define NB 4096
#define NT 512
#define NS 6
#define NF 12
#define STRIDE (NB * NS)   // floats per time-slice in [t][b][s] layout = 24576

// Scratch: emission logp, overwritten in-place with Viterbi values v_t by the
// forward kernel. 8 slack time-slices so the software prefetch can read past
// t=511 without guards.
__device__ float g_emis[(NT + 8) * NB * NS];   // [t][b][s]
__device__ float g_logtrans[NS * NS];          // [p][s]  log softmax rows + log(+1e-8)
__device__ float g_loginit[NS];
// emission params: inv2[72], means*inv2[72], c[6], logdet[6]
__device__ float g_epar[2 * NS * NF + 2 * NS];

// ---------------------------------------------------------------------------
// K0: tiny parameter precompute (runs in ~a microsecond, single thread)
// ---------------------------------------------------------------------------
__global__ void k_setup(const float* __restrict__ trans,
                        const float* __restrict__ init,
                        const float* __restrict__ means,
                        const float* __restrict__ logsc)
{
    if (threadIdx.x != 0 || blockIdx.x != 0) return;

    // log(softmax(row) + 1e-8)
    for (int p = 0; p < NS; p++) {
        float m = trans[p * NS];
        for (int s = 1; s < NS; s++) m = fmaxf(m, trans[p * NS + s]);
        float sum = 0.f;
        for (int s = 0; s < NS; s++) sum += expf(trans[p * NS + s] - m);
        for (int s = 0; s < NS; s++)
            g_logtrans[p * NS + s] = logf(expf(trans[p * NS + s] - m) / sum + 1e-8f);
    }
    {
        float m = init[0];
        for (int s = 1; s < NS; s++) m = fmaxf(m, init[s]);
        float sum = 0.f;
        for (int s = 0; s < NS; s++) sum += expf(init[s] - m);
        for (int s = 0; s < NS; s++)
            g_loginit[s] = logf(expf(init[s] - m) / sum + 1e-8f);
    }
    for (int s = 0; s < NS; s++) {
        float c = 0.f, ld = 0.f;
        for (int f = 0; f < NF; f++) {
            float x    = logsc[s * NF + f];
            float sc   = log1pf(expf(x)) + 1e-6f;   // softplus + 1e-6
            float den  = sc + 1e-6f;
            float inv2 = 1.0f / (den * den);
            float mu   = means[s * NF + f];
            g_epar[s * NF + f]           = inv2;
            g_epar[NS * NF + s * NF + f] = mu * inv2;
            c  += mu * mu * inv2;
            ld += logf(sc);
        }
        g_epar[2 * NS * NF + s]      = c;
        g_epar[2 * NS * NF + NS + s] = ld;
    }
}

// ---------------------------------------------------------------------------
// K1: emission logp.  Block = 32 b x 8 t tile.  Coalesced obs reads (rows of
// 48B, 8t contiguous per b) and coalesced [t][b][s] writes via a shared tile.
// Row pad 196 (not 192) so the 8 tt-values hit distinct banks on STS.
// ---------------------------------------------------------------------------
#define TILE_PAD 196

__global__ void k_emis(const float* __restrict__ obs)
{
    __shared__ float sp[156];
    __shared__ float tile[8 * TILE_PAD];

    int tid = threadIdx.x;
    if (tid < 156) sp[tid] = g_epar[tid];
    __syncthreads();

    int tt = tid & 7, bb = tid >> 3;
    int t = blockIdx.x * 8 + tt;
    int b = blockIdx.y * 32 + bb;

    const float4* op = (const float4*)(obs + ((size_t)b * NT + t) * NF);
    float4 o0 = op[0], o1 = op[1], o2v = op[2];
    float o[12] = { o0.x, o0.y, o0.z, o0.w, o1.x, o1.y, o1.z, o1.w,
                    o2v.x, o2v.y, o2v.z, o2v.w };
    float osq[12];
#pragma unroll
    for (int f = 0; f < 12; f++) osq[f] = o[f] * o[f];

#pragma unroll
    for (int s = 0; s < NS; s++) {
        float a1 = 0.f, a2 = 0.f;
#pragma unroll
        for (int f = 0; f < 12; f++) {
            a1 = fmaf(osq[f], sp[s * 12 + f], a1);        // e1 term
            a2 = fmaf(o[f],   sp[72 + s * 12 + f], a2);   // e2 term
        }
        float e = -0.5f * (a1 - 2.f * a2 + sp[144 + s]) - sp[150 + s];
        tile[tt * TILE_PAD + bb * 6 + s] = e;
    }
    __syncthreads();

    size_t base = (size_t)(blockIdx.x * 8) * STRIDE + (size_t)blockIdx.y * 32 * NS;
#pragma unroll
    for (int k = 0; k < 6; k++) {
        int idx = k * 256 + tid;          // 0..1535 over logical [tt][r], r = bb*6+s in [0,192)
        int tt2 = idx / 192;
        int r   = idx - tt2 * 192;
        g_emis[base + (size_t)tt2 * STRIDE + r] = tile[tt2 * TILE_PAD + r];
    }
}

// ---------------------------------------------------------------------------
// K2: forward Viterbi.  1 thread per batch, blockDim 32 -> 128 blocks spread
// over the SMs.  Per-step: 3 prefetch LDG.64 (depth-4 ring), 36 FADD,
// 30 FMNMX, 6 FADD, 3 STG.64.  v_t overwrites the emission slot in-place.
// ---------------------------------------------------------------------------
__global__ void k_fwd()
{
    int b = blockIdx.x * 32 + threadIdx.x;

    float lt[36];
#pragma unroll
    for (int i = 0; i < 36; i++) lt[i] = g_logtrans[i];

    float* p = g_emis + (size_t)b * NS;   // t=0 slice for this batch

    float v[6];
#pragma unroll
    for (int s = 0; s < 6; s++) { v[s] = g_loginit[s] + p[s]; p[s] = v[s]; }

    // prefetch ring: slot u holds e(t) where (t-1)&3 == u
    float eb[4][6];
#pragma unroll
    for (int k = 0; k < 4; k++) {
        const float2* q = (const float2*)(p + (size_t)(1 + k) * STRIDE);
        float2 a = q[0], bq = q[1], c = q[2];
        eb[k][0] = a.x; eb[k][1] = a.y; eb[k][2] = bq.x;
        eb[k][3] = bq.y; eb[k][4] = c.x; eb[k][5] = c.y;
    }

    for (int tb = 1; tb < 512; tb += 4) {
#pragma unroll
        for (int u = 0; u < 4; u++) {
            int t = tb + u;
            if (t < 512) {
                float e[6];
#pragma unroll
                for (int s = 0; s < 6; s++) e[s] = eb[u][s];
                // prefetch e(t+4); t+4 may land in the zero slack region (never consumed)
                {
                    const float2* q = (const float2*)(p + (size_t)(t + 4) * STRIDE);
                    float2 a = q[0], bq = q[1], c = q[2];
                    eb[u][0] = a.x; eb[u][1] = a.y; eb[u][2] = bq.x;
                    eb[u][3] = bq.y; eb[u][4] = c.x; eb[u][5] = c.y;
                }
                float nv[6];
#pragma unroll
                for (int s = 0; s < 6; s++) {
                    float m = v[0] + lt[s];
                    m = fmaxf(m, v[1] + lt[6  + s]);
                    m = fmaxf(m, v[2] + lt[12 + s]);
                    m = fmaxf(m, v[3] + lt[18 + s]);
                    m = fmaxf(m, v[4] + lt[24 + s]);
                    m = fmaxf(m, v[5] + lt[30 + s]);
                    nv[s] = m + e[s];
                }
#pragma unroll
                for (int s = 0; s < 6; s++) v[s] = nv[s];
                float2* w = (float2*)(p + (size_t)t * STRIDE);
                w[0] = make_float2(v[0], v[1]);
                w[1] = make_float2(v[2], v[3]);
                w[2] = make_float2(v[4], v[5]);
            }
        }
    }
}

// ---------------------------------------------------------------------------
// K3: backtrace.  path[t] = first-argmax_p( v_t[p] + LT[p][path[t+1]] ).
// Depth-8 prefetch ring (8 x ~35cyc > L2 hit latency).  Path staged in a
// 32x33 shared tile, flushed as coalesced 128B rows every 32 steps.
// ---------------------------------------------------------------------------
#define BSTEP(T_, SL_) do {                                                   \
    int t_ = (T_);                                                            \
    float r0 = rb[SL_][0], r1 = rb[SL_][1], r2 = rb[SL_][2];                  \
    float r3 = rb[SL_][3], r4 = rb[SL_][4], r5 = rb[SL_][5];                  \
    if (t_ >= 8) {                                                            \
        const float2* q_ = (const float2*)(p + (size_t)(t_ - 8) * STRIDE);    \
        float2 a_ = q_[0], b_ = q_[1], c_ = q_[2];                            \
        rb[SL_][0] = a_.x; rb[SL_][1] = a_.y; rb[SL_][2] = b_.x;              \
        rb[SL_][3] = b_.y; rb[SL_][4] = c_.x; rb[SL_][5] = c_.y;              \
    }                                                                         \
    float4 L0 = *(const float4*)&ltt[cur * 8];                                \
    float2 L1 = *(const float2*)&ltt[cur * 8 + 4];                            \
    float c0 = r0 + L0.x, c1 = r1 + L0.y, c2 = r2 + L0.z;                     \
    float c3 = r3 + L0.w, c4 = r4 + L1.x, c5 = r5 + L1.y;                     \
    float m_ = c0; int nc_ = 0;                                               \
    if (c1 > m_) { m_ = c1; nc_ = 1; }                                        \
    if (c2 > m_) { m_ = c2; nc_ = 2; }                                        \
    if (c3 > m_) { m_ = c3; nc_ = 3; }                                        \
    if (c4 > m_) { m_ = c4; nc_ = 4; }                                        \
    if (c5 > m_) { m_ = c5; nc_ = 5; }                                        \
    cur = nc_;                                                                \
    tile[lane * 33 + (t_ & 31)] = (float)cur;                                 \
    if ((t_ & 31) == 0) {                                                     \
        __syncwarp();                                                         \
        if (write_path) {                                                     \
            for (int r_ = 0; r_ < 32; r_++)                                   \
                out[(size_t)(b0 + r_) * NT + t_ + lane] = tile[r_ * 33 + lane];\
        }                                                                     \
        __syncwarp();                                                         \
    }                                                                         \
} while (0)

__global__ void k_bwd(float* __restrict__ out, int write_path,
                      int write_score, int score_off)
{
    __shared__ float ltt[6 * 8];    // ltt[s][p] = LT[p][s], rows padded to 32B
    __shared__ float tile[32 * 33];

    int lane = threadIdx.x;
    for (int i = lane; i < 36; i += 32) {
        int pp = i / 6, ss = i - pp * 6;
        ltt[ss * 8 + pp] = g_logtrans[pp * 6 + ss];
    }
    __syncthreads();

    int b0 = blockIdx.x * 32;
    int b  = b0 + lane;
    const float* p = g_emis + (size_t)b * NS;   // holds v_t now

    int cur;
    {
        const float2* q = (const float2*)(p + (size_t)511 * STRIDE);
        float2 a = q[0], bq = q[1], c = q[2];
        float x0 = a.x, x1 = a.y, x2 = bq.x, x3 = bq.y, x4 = c.x, x5 = c.y;
        float m = x0; cur = 0;
        if (x1 > m) { m = x1; cur = 1; }
        if (x2 > m) { m = x2; cur = 2; }
        if (x3 > m) { m = x3; cur = 3; }
        if (x4 > m) { m = x4; cur = 4; }
        if (x5 > m) { m = x5; cur = 5; }
        if (write_score) out[score_off + b] = m;
        tile[lane * 33 + 31] = (float)cur;      // path[511]
    }

    // preload v_t for t = 510..503 into slot t&7
    float rb[8][6];
#pragma unroll
    for (int k = 0; k < 8; k++) {
        int t = 510 - k;
        const float2* q = (const float2*)(p + (size_t)t * STRIDE);
        float2 a = q[0], bq = q[1], c = q[2];
        int sl = t & 7;                          // 6,5,4,3,2,1,0,7 — compile-time after unroll
        rb[sl][0] = a.x; rb[sl][1] = a.y; rb[sl][2] = bq.x;
        rb[sl][3] = bq.y; rb[sl][4] = c.x; rb[sl][5] = c.y;
    }

    // peel to 8-alignment: t = 510..504 (slots 6..0)
    BSTEP(510, 6); BSTEP(509, 5); BSTEP(508, 4); BSTEP(507, 3);
    BSTEP(506, 2); BSTEP(505, 1); BSTEP(504, 0);

    for (int tb = 503; tb >= 7; tb -= 8) {       // tb ≡ 7 (mod 8)
        BSTEP(tb - 0, 7); BSTEP(tb - 1, 6); BSTEP(tb - 2, 5); BSTEP(tb - 3, 4);
        BSTEP(tb - 4, 3); BSTEP(tb - 5, 2); BSTEP(tb - 6, 1); BSTEP(tb - 7, 0);
    }
}

// ---------------------------------------------------------------------------
extern "C" void kernel_launch(void* const* d_in, const int* in_sizes, int n_in,
                              void* d_out, int out_size)
{
    (void)in_sizes; (void)n_in;
    const float* obs  = (const float*)d_in[0];
    const float* tr   = (const float*)d_in[1];
    const float* ini  = (const float*)d_in[2];
    const float* mu   = (const float*)d_in[3];
    const float* lsc  = (const float*)d_in[4];
    float* out = (float*)d_out;

    const int PT = NB * NT;
    int write_path = 0, write_score = 0, score_off = 0;
    if (out_size >= PT + NB)      { write_path = 1; write_score = 1; score_off = PT; }
    else if (out_size >= PT)      { write_path = 1; }
    else                          { write_score = 1; score_off = 0; }

    k_setup<<<1, 32>>>(tr, ini, mu, lsc);
    k_emis<<<dim3(NT / 8, NB / 32), 256>>>(obs);
    k_fwd<<<NB / 32, 32>>>();
    k_bwd<<<NB / 32, 32>>>(out, write_path, write_score, score_off);
}